// round 3
// baseline (speedup 1.0000x reference)
#include <cuda_runtime.h>
#include <cuda_bf16.h>

// Problem constants: H=32, T=8192, D=128
#define RP_H 32
#define RP_T 8192
#define RP_D 128
#define RP_ROWS (RP_H * RP_T)              // 262144 rows
#define RP_RPW 4                           // rows per warp (consecutive t, same head)
#define RP_THREADS 256                     // 8 warps / block
#define RP_WARPS (RP_ROWS / RP_RPW)        // 65536 warps
#define RP_BLOCKS (RP_WARPS / (RP_THREADS / 32))  // 8192 blocks

// t-major warp mapping: gwarp = tchunk*32 + h. All 32 heads of one t-chunk are
// handled by 32 consecutive warps -> concurrently-active cos/sin window is tiny
// and L2-resident by construction. x / out are pure streams -> ldcs/stcs.
__global__ __launch_bounds__(RP_THREADS) void rope_minmax_kernel(
    const float* __restrict__ x,
    const float* __restrict__ cosb,
    const float* __restrict__ sinb,
    float* __restrict__ out,
    float* __restrict__ obs_max,
    float* __restrict__ obs_min)
{
    const unsigned FULL = 0xffffffffu;
    int gwarp  = (blockIdx.x * RP_THREADS + threadIdx.x) >> 5;  // 0..RP_WARPS-1
    int lane   = threadIdx.x & 31;
    int h      = gwarp & (RP_H - 1);        // head
    int tchunk = gwarp >> 5;                // 0..2047
    int t0     = tchunk * RP_RPW;           // first t of this warp's chunk
    size_t row0 = (size_t)h * RP_T + t0;    // first row index (multiple of 4)

    // ---- front-batched loads: 12 independent LDG.128 ----
    float4 v[RP_RPW], c[RP_RPW], s[RP_RPW];
    #pragma unroll
    for (int r = 0; r < RP_RPW; r++) {
        // x: streaming, evict-first
        v[r] = __ldcs(reinterpret_cast<const float4*>(x + (row0 + r) * RP_D) + lane);
        // cos/sin: reused across 32 heads -> default (L2-resident) policy
        c[r] = reinterpret_cast<const float4*>(cosb + (size_t)(t0 + r) * RP_D)[lane];
        s[r] = reinterpret_cast<const float4*>(sinb + (size_t)(t0 + r) * RP_D)[lane];
    }

    float sign = (lane < 16) ? -1.0f : 1.0f;
    float mx[RP_RPW], mn[RP_RPW];

    #pragma unroll
    for (int r = 0; r < RP_RPW; r++) {
        // partner half (elements i +/- 64) lives in lane ^ 16
        float4 p;
        p.x = __shfl_xor_sync(FULL, v[r].x, 16);
        p.y = __shfl_xor_sync(FULL, v[r].y, 16);
        p.z = __shfl_xor_sync(FULL, v[r].z, 16);
        p.w = __shfl_xor_sync(FULL, v[r].w, 16);

        float4 o;
        o.x = fmaf(sign * p.x, s[r].x, v[r].x * c[r].x);
        o.y = fmaf(sign * p.y, s[r].y, v[r].y * c[r].y);
        o.z = fmaf(sign * p.z, s[r].z, v[r].z * c[r].z);
        o.w = fmaf(sign * p.w, s[r].w, v[r].w * c[r].w);

        // out: streaming store, evict-first
        __stcs(reinterpret_cast<float4*>(out + (row0 + r) * RP_D) + lane, o);

        mx[r] = fmaxf(fmaxf(o.x, o.y), fmaxf(o.z, o.w));
        mn[r] = fminf(fminf(o.x, o.y), fminf(o.z, o.w));
    }

    // ---- 4 interleaved butterfly reductions (ILP hides SHFL latency) ----
    #pragma unroll
    for (int off = 16; off > 0; off >>= 1) {
        #pragma unroll
        for (int r = 0; r < RP_RPW; r++) {
            mx[r] = fmaxf(mx[r], __shfl_xor_sync(FULL, mx[r], off));
            mn[r] = fminf(mn[r], __shfl_xor_sync(FULL, mn[r], off));
        }
    }

    if (lane == 0) {
        // row0 is a multiple of 4 -> 16B-aligned vector stores
        *reinterpret_cast<float4*>(obs_max + row0) = make_float4(mx[0], mx[1], mx[2], mx[3]);
        *reinterpret_cast<float4*>(obs_min + row0) = make_float4(mn[0], mn[1], mn[2], mn[3]);
    }
}

extern "C" void kernel_launch(void* const* d_in, const int* in_sizes, int n_in,
                              void* d_out, int out_size) {
    // Input order: x, scale_x (unused), cos, scale_cos (unused), sin, scale_sin (unused)
    const float* x    = (const float*)d_in[0];
    const float* cosb = (const float*)d_in[2];
    const float* sinb = (const float*)d_in[4];

    float* out     = (float*)d_out;                    // H*T*D
    float* obs_max = out + (size_t)RP_ROWS * RP_D;     // H*T
    float* obs_min = obs_max + (size_t)RP_ROWS;        // H*T

    rope_minmax_kernel<<<RP_BLOCKS, RP_THREADS>>>(x, cosb, sinb, out, obs_max, obs_min);
}

// round 4
// speedup vs baseline: 1.0373x; 1.0373x over previous
#include <cuda_runtime.h>
#include <cuda_bf16.h>

// Problem constants: H=32, T=8192, D=128
#define RP_H 32
#define RP_T 8192
#define RP_D 128
#define RP_ROWS (RP_H * RP_T)              // 262144 rows
#define RP_RPW 4                           // rows per warp
#define RP_THREADS 256                     // 8 warps / block
#define RP_WARPS (RP_ROWS / RP_RPW)        // 65536 warps
#define RP_BLOCKS (RP_WARPS / (RP_THREADS / 32))  // 8192 blocks

// One warp handles 4 consecutive rows (row-major mapping: same head, t..t+3).
// The four DRAM-critical x loads are issued first (queue head), then the
// L2-resident cos/sin loads. min 6 blocks/SM -> 48 warps resident.
__global__ __launch_bounds__(RP_THREADS, 6) void rope_minmax_kernel(
    const float* __restrict__ x,
    const float* __restrict__ cosb,
    const float* __restrict__ sinb,
    float* __restrict__ out,
    float* __restrict__ obs_max,
    float* __restrict__ obs_min)
{
    const unsigned FULL = 0xffffffffu;
    int gwarp = (blockIdx.x * RP_THREADS + threadIdx.x) >> 5;  // 0..RP_WARPS-1
    int lane  = threadIdx.x & 31;
    int r0    = gwarp * RP_RPW;                 // first row (multiple of 4)
    int t0    = r0 & (RP_T - 1);                // first t (rows share head)

    // ---- DRAM-bound x loads first: 4 independent LDG.128 at queue head ----
    float4 v[RP_RPW];
    #pragma unroll
    for (int r = 0; r < RP_RPW; r++)
        v[r] = reinterpret_cast<const float4*>(x + (size_t)(r0 + r) * RP_D)[lane];

    // ---- L2-resident table loads behind them ----
    float4 c[RP_RPW], s[RP_RPW];
    #pragma unroll
    for (int r = 0; r < RP_RPW; r++) {
        c[r] = reinterpret_cast<const float4*>(cosb + (size_t)(t0 + r) * RP_D)[lane];
        s[r] = reinterpret_cast<const float4*>(sinb + (size_t)(t0 + r) * RP_D)[lane];
    }

    float sign = (lane < 16) ? -1.0f : 1.0f;
    float mx[RP_RPW], mn[RP_RPW];

    #pragma unroll
    for (int r = 0; r < RP_RPW; r++) {
        // partner half (elements i +/- 64) lives in lane ^ 16
        float4 p;
        p.x = __shfl_xor_sync(FULL, v[r].x, 16);
        p.y = __shfl_xor_sync(FULL, v[r].y, 16);
        p.z = __shfl_xor_sync(FULL, v[r].z, 16);
        p.w = __shfl_xor_sync(FULL, v[r].w, 16);

        float4 o;
        o.x = fmaf(sign * p.x, s[r].x, v[r].x * c[r].x);
        o.y = fmaf(sign * p.y, s[r].y, v[r].y * c[r].y);
        o.z = fmaf(sign * p.z, s[r].z, v[r].z * c[r].z);
        o.w = fmaf(sign * p.w, s[r].w, v[r].w * c[r].w);

        reinterpret_cast<float4*>(out + (size_t)(r0 + r) * RP_D)[lane] = o;

        mx[r] = fmaxf(fmaxf(o.x, o.y), fmaxf(o.z, o.w));
        mn[r] = fminf(fminf(o.x, o.y), fminf(o.z, o.w));
    }

    // ---- 4 interleaved butterfly reductions (ILP hides SHFL latency) ----
    #pragma unroll
    for (int off = 16; off > 0; off >>= 1) {
        #pragma unroll
        for (int r = 0; r < RP_RPW; r++) {
            mx[r] = fmaxf(mx[r], __shfl_xor_sync(FULL, mx[r], off));
            mn[r] = fminf(mn[r], __shfl_xor_sync(FULL, mn[r], off));
        }
    }

    if (lane == 0) {
        // r0 is a multiple of 4 -> 16B-aligned vector stores
        *reinterpret_cast<float4*>(obs_max + r0) = make_float4(mx[0], mx[1], mx[2], mx[3]);
        *reinterpret_cast<float4*>(obs_min + r0) = make_float4(mn[0], mn[1], mn[2], mn[3]);
    }
}

extern "C" void kernel_launch(void* const* d_in, const int* in_sizes, int n_in,
                              void* d_out, int out_size) {
    // Input order: x, scale_x (unused), cos, scale_cos (unused), sin, scale_sin (unused)
    const float* x    = (const float*)d_in[0];
    const float* cosb = (const float*)d_in[2];
    const float* sinb = (const float*)d_in[4];

    float* out     = (float*)d_out;                    // H*T*D
    float* obs_max = out + (size_t)RP_ROWS * RP_D;     // H*T
    float* obs_min = obs_max + (size_t)RP_ROWS;        // H*T

    rope_minmax_kernel<<<RP_BLOCKS, RP_THREADS>>>(x, cosb, sinb, out, obs_max, obs_min);
}